// round 3
// baseline (speedup 1.0000x reference)
#include <cuda_runtime.h>
#include <cuda_bf16.h>
#include <math.h>

// Problem constants
#define N_NODES 50000
#define N_EDGES 800000
#define IN_CH   128
#define HID     256
#define OUT_CH  40

// -------- static device scratch (allocation-free) --------
__device__ float g_buf0[(size_t)N_NODES * HID];   // h (post-GEMM features)
__device__ float g_buf1[(size_t)N_NODES * HID];   // agg layer1 -> x2
__device__ float g_buf2[(size_t)N_NODES * HID];   // agg layer2 -> x3

// ---------------------------------------------------------
// fp32 register-tiled GEMM: C[M,N] = A[M,K] @ B[K,N]
// BM=128, BN=64, BK=16, 256 threads, 8x4 per thread
// ---------------------------------------------------------
#define BM 128
#define BN 64
#define BKK 16
#define TM 8
#define TN 4

__global__ __launch_bounds__(256) void gemm_kernel(
    const float* __restrict__ A, const float* __restrict__ B,
    float* __restrict__ C, int M, int N, int K)
{
    __shared__ float As[BKK][BM];
    __shared__ float Bs[BKK][BN];

    const int tid = threadIdx.x;
    const int bm = blockIdx.y * BM;
    const int bn = blockIdx.x * BN;
    const int tx = tid & 15;       // N direction (16 * TN = 64)
    const int ty = tid >> 4;       // M direction (16 * TM = 128)

    float acc[TM][TN];
#pragma unroll
    for (int i = 0; i < TM; i++)
#pragma unroll
        for (int j = 0; j < TN; j++) acc[i][j] = 0.f;

    const int ar = tid >> 4;   // 0..15
    const int ac = tid & 15;   // 0..15
    const int br = tid >> 6;   // 0..3
    const int bc = tid & 63;   // 0..63

    for (int k0 = 0; k0 < K; k0 += BKK) {
        // load A tile [BM][BK] transposed -> As[ac][row]
#pragma unroll
        for (int i = 0; i < 8; i++) {
            int row = ar + i * 16;
            int grow = bm + row;
            float v = 0.f;
            if (grow < M) v = A[(long)grow * K + k0 + ac];
            As[ac][row] = v;
        }
        // load B tile [BK][BN]
#pragma unroll
        for (int i = 0; i < 4; i++) {
            int row = br + i * 4;
            int gcol = bn + bc;
            float v = 0.f;
            if (gcol < N) v = B[(long)(k0 + row) * N + gcol];
            Bs[row][bc] = v;
        }
        __syncthreads();

#pragma unroll
        for (int k = 0; k < BKK; k++) {
            float ra[TM], rb[TN];
#pragma unroll
            for (int i = 0; i < TM; i++) ra[i] = As[k][ty * TM + i];
#pragma unroll
            for (int j = 0; j < TN; j++) rb[j] = Bs[k][tx * TN + j];
#pragma unroll
            for (int i = 0; i < TM; i++)
#pragma unroll
                for (int j = 0; j < TN; j++)
                    acc[i][j] += ra[i] * rb[j];
        }
        __syncthreads();
    }

#pragma unroll
    for (int i = 0; i < TM; i++) {
        int grow = bm + ty * TM + i;
        if (grow >= M) continue;
#pragma unroll
        for (int j = 0; j < TN; j++) {
            int gcol = bn + tx * TN + j;
            if (gcol < N) C[(long)grow * N + gcol] = acc[i][j];
        }
    }
}

// ---------------------------------------------------------
// zero fill
// ---------------------------------------------------------
__global__ void zero_kernel(float* __restrict__ p, long n)
{
    long i = (long)blockIdx.x * blockDim.x + threadIdx.x;
    if (i < n) p[i] = 0.f;
}

// ---------------------------------------------------------
// vector float4 reduction (no return) -- sm_90+
// ---------------------------------------------------------
__device__ __forceinline__ void redAdd4(float4* addr, float4 v)
{
    asm volatile("red.global.add.v4.f32 [%0], {%1,%2,%3,%4};"
                 :: "l"(addr), "f"(v.x), "f"(v.y), "f"(v.z), "f"(v.w)
                 : "memory");
}

// ---------------------------------------------------------
// scatter-add for 256-wide features: agg[dst] += ew * h[src]
// one thread per (edge, float4-chunk), 64 chunks per edge
// ---------------------------------------------------------
__global__ __launch_bounds__(256) void scatter256_kernel(
    const int* __restrict__ src, const int* __restrict__ dst,
    const float* __restrict__ ew,
    const float* __restrict__ h, float* __restrict__ agg)
{
    long t = (long)blockIdx.x * blockDim.x + threadIdx.x;
    long e = t >> 6;
    int  c = (int)(t & 63);
    if (e >= N_EDGES) return;
    int s = src[e];
    int d = dst[e];
    float w = ew[e];
    float4 v = reinterpret_cast<const float4*>(h)[(long)s * 64 + c];
    v.x *= w; v.y *= w; v.z *= w; v.w *= w;
    redAdd4(&reinterpret_cast<float4*>(agg)[(long)d * 64 + c], v);
}

// ---------------------------------------------------------
// scatter-add for 40-wide features (10 float4 chunks per edge)
// ---------------------------------------------------------
__global__ __launch_bounds__(256) void scatter40_kernel(
    const int* __restrict__ src, const int* __restrict__ dst,
    const float* __restrict__ ew,
    const float* __restrict__ h, float* __restrict__ agg)
{
    long t = (long)blockIdx.x * blockDim.x + threadIdx.x;
    long e = t / 10;
    int  c = (int)(t - e * 10);
    if (e >= N_EDGES) return;
    int s = src[e];
    int d = dst[e];
    float w = ew[e];
    float4 v = reinterpret_cast<const float4*>(h)[(long)s * 10 + c];
    v.x *= w; v.y *= w; v.z *= w; v.w *= w;
    redAdd4(&reinterpret_cast<float4*>(agg)[(long)d * 10 + c], v);
}

// ---------------------------------------------------------
// x = relu(x + b), C-wide rows
// ---------------------------------------------------------
__global__ void bias_relu_kernel(float* __restrict__ p,
                                 const float* __restrict__ b, long n, int C)
{
    long i = (long)blockIdx.x * blockDim.x + threadIdx.x;
    if (i < n) {
        float v = p[i] + b[(int)(i & (C - 1))];  // C is power of 2 (256)
        p[i] = v > 0.f ? v : 0.f;
    }
}

// ---------------------------------------------------------
// out = log_softmax(out + b), rows of 40, one warp per row
// ---------------------------------------------------------
__global__ __launch_bounds__(256) void logsoftmax40_kernel(
    float* __restrict__ out, const float* __restrict__ b, int M)
{
    int warp = (int)(((long)blockIdx.x * blockDim.x + threadIdx.x) >> 5);
    int lane = threadIdx.x & 31;
    if (warp >= M) return;
    float* row = out + (long)warp * OUT_CH;

    float v0 = row[lane] + b[lane];
    float v1 = (lane < 8) ? (row[32 + lane] + b[32 + lane]) : -INFINITY;

    float m = fmaxf(v0, v1);
#pragma unroll
    for (int o = 16; o > 0; o >>= 1)
        m = fmaxf(m, __shfl_xor_sync(0xFFFFFFFFu, m, o));

    float s = __expf(v0 - m) + ((lane < 8) ? __expf(v1 - m) : 0.f);
#pragma unroll
    for (int o = 16; o > 0; o >>= 1)
        s += __shfl_xor_sync(0xFFFFFFFFu, s, o);

    float lse = m + logf(s);
    row[lane] = v0 - lse;
    if (lane < 8) row[32 + lane] = v1 - lse;
}

// ---------------------------------------------------------
// launch
// ---------------------------------------------------------
extern "C" void kernel_launch(void* const* d_in, const int* in_sizes, int n_in,
                              void* d_out, int out_size)
{
    const float* x  = (const float*)d_in[0];
    const int*   ei = (const int*)d_in[1];
    const float* ew = (const float*)d_in[2];
    const float* W1 = (const float*)d_in[3];
    const float* b1 = (const float*)d_in[4];
    const float* W2 = (const float*)d_in[5];
    const float* b2 = (const float*)d_in[6];
    const float* W3 = (const float*)d_in[7];
    const float* b3 = (const float*)d_in[8];
    float* out = (float*)d_out;

    const int* src = ei;            // edge_index[0]
    const int* dst = ei + N_EDGES;  // edge_index[1]

    float *buf0, *buf1, *buf2;
    cudaGetSymbolAddress((void**)&buf0, g_buf0);
    cudaGetSymbolAddress((void**)&buf1, g_buf1);
    cudaGetSymbolAddress((void**)&buf2, g_buf2);

    const long NF = (long)N_NODES * HID;         // 12.8M
    const long NO = (long)N_NODES * OUT_CH;      // 2M

    dim3 gemm_grid1((HID + BN - 1) / BN, (N_NODES + BM - 1) / BM);
    dim3 gemm_grid3((OUT_CH + BN - 1) / BN, (N_NODES + BM - 1) / BM);

    const long sc256_threads = (long)N_EDGES * 64;
    const int  sc256_blocks  = (int)((sc256_threads + 255) / 256);
    const long sc40_threads  = (long)N_EDGES * 10;
    const int  sc40_blocks   = (int)((sc40_threads + 255) / 256);

    // ---- layer 1 ----
    gemm_kernel<<<gemm_grid1, 256>>>(x, W1, buf0, N_NODES, HID, IN_CH);
    zero_kernel<<<(int)((NF + 255) / 256), 256>>>(buf1, NF);
    scatter256_kernel<<<sc256_blocks, 256>>>(src, dst, ew, buf0, buf1);
    bias_relu_kernel<<<(int)((NF + 255) / 256), 256>>>(buf1, b1, NF, HID);

    // ---- layer 2 ----
    gemm_kernel<<<gemm_grid1, 256>>>(buf1, W2, buf0, N_NODES, HID, HID);
    zero_kernel<<<(int)((NF + 255) / 256), 256>>>(buf2, NF);
    scatter256_kernel<<<sc256_blocks, 256>>>(src, dst, ew, buf0, buf2);
    bias_relu_kernel<<<(int)((NF + 255) / 256), 256>>>(buf2, b2, NF, HID);

    // ---- layer 3 ----
    gemm_kernel<<<gemm_grid3, 256>>>(buf2, W3, buf0, N_NODES, OUT_CH, HID);
    zero_kernel<<<(int)((NO + 255) / 256), 256>>>(out, NO);
    scatter40_kernel<<<sc40_blocks, 256>>>(src, dst, ew, buf0, out);
    logsoftmax40_kernel<<<(N_NODES * 32 + 255) / 256, 256>>>(out, b3, N_NODES);
}

// round 4
// speedup vs baseline: 1.5798x; 1.5798x over previous
#include <cuda_runtime.h>
#include <cuda_bf16.h>
#include <math.h>
#include <stdint.h>

// Problem constants
#define N_NODES 50000
#define N_EDGES 800000
#define IN_CH   128
#define HID     256
#define OUT_CH  40

// -------- static device scratch (allocation-free) --------
__device__ float g_buf0[(size_t)N_NODES * HID];   // h (post-GEMM features)
__device__ float g_buf1[(size_t)N_NODES * HID];   // agg layer1
__device__ float g_buf2[(size_t)N_NODES * HID];   // agg layer2

// =========================================================
// tf32 tensor-core GEMM: C[M,N] = op(A)[M,K] @ B[K,N]
//   op(A) = FUSE ? relu(A + bias[k]) : A
// Block tile 128x64x32, 256 threads = 8 warps (4x2), warp tile 32x32,
// mma.sync m16n8k8 tf32.
// =========================================================
#define GBM 128
#define GBN 64
#define GBK 32
#define ASTRIDE 136   // GBM + 8  (stride%32 == 8 -> k-groups hit disjoint banks)
#define BSTRIDE 72    // GBN + 8

__device__ __forceinline__ uint32_t f2tf(float f) {
    uint32_t r;
    asm("cvt.rna.tf32.f32 %0, %1;" : "=r"(r) : "f"(f));
    return r;
}

__device__ __forceinline__ void mma_tf32(float* d, const uint32_t* a, const uint32_t* b) {
    asm volatile(
        "mma.sync.aligned.m16n8k8.row.col.f32.tf32.tf32.f32 "
        "{%0,%1,%2,%3}, {%4,%5,%6,%7}, {%8,%9}, {%0,%1,%2,%3};\n"
        : "+f"(d[0]), "+f"(d[1]), "+f"(d[2]), "+f"(d[3])
        : "r"(a[0]), "r"(a[1]), "r"(a[2]), "r"(a[3]),
          "r"(b[0]), "r"(b[1]));
}

template <bool FUSE>
__global__ __launch_bounds__(256) void gemm_tf32(
    const float* __restrict__ A, const float* __restrict__ B,
    const float* __restrict__ bias, float* __restrict__ C,
    int M, int N, int K)
{
    __shared__ uint32_t As[GBK * ASTRIDE];  // stored k-major: As[k][m], m swizzled
    __shared__ uint32_t Bs[GBK * BSTRIDE];  // Bs[k][n]

    const int tid  = threadIdx.x;
    const int warp = tid >> 5;
    const int lane = tid & 31;
    const int bm = blockIdx.y * GBM;
    const int bn = blockIdx.x * GBN;

    const int wm = (warp >> 1) * 32;   // 4 warps along M
    const int wn = (warp & 1) * 32;    // 2 warps along N

    const int qr = lane >> 2;          // groupID (T/4)
    const int qc = lane & 3;           // threadID_in_group (T%4)

    float acc[2][4][4];
#pragma unroll
    for (int i = 0; i < 2; i++)
#pragma unroll
        for (int j = 0; j < 4; j++)
#pragma unroll
            for (int t = 0; t < 4; t++) acc[i][j][t] = 0.f;

    for (int k0 = 0; k0 < K; k0 += GBK) {
        // ---- load A tile 128x32 (1024 float4, 4 per thread), transpose+swizzle into smem ----
#pragma unroll
        for (int i = 0; i < 4; i++) {
            int idx = tid + i * 256;
            int row = idx >> 3;           // 0..127
            int c4  = (idx & 7) * 4;      // 0,4,...,28
            float4 v = make_float4(0.f, 0.f, 0.f, 0.f);
            int gr = bm + row;
            if (gr < M) {
                v = *reinterpret_cast<const float4*>(A + (long)gr * K + k0 + c4);
                if (FUSE) {
                    v.x = fmaxf(v.x + bias[k0 + c4 + 0], 0.f);
                    v.y = fmaxf(v.y + bias[k0 + c4 + 1], 0.f);
                    v.z = fmaxf(v.z + bias[k0 + c4 + 2], 0.f);
                    v.w = fmaxf(v.w + bias[k0 + c4 + 3], 0.f);
                }
            }
            const float* pv = &v.x;
#pragma unroll
            for (int j = 0; j < 4; j++) {
                int kk = c4 + j;
                int sm = row ^ (((kk >> 2) & 7) << 3);   // swizzle m by k-quad
                As[kk * ASTRIDE + sm] = f2tf(pv[j]);
            }
        }
        // ---- load B tile 32x64 (512 float4, 2 per thread) ----
#pragma unroll
        for (int i = 0; i < 2; i++) {
            int idx = tid + i * 256;
            int row = idx >> 4;           // 0..31 (k)
            int c4  = (idx & 15) * 4;     // 0..60 (n)
            float4 v = make_float4(0.f, 0.f, 0.f, 0.f);
            int gc = bn + c4;
            if (gc + 3 < N) {
                v = *reinterpret_cast<const float4*>(B + (long)(k0 + row) * N + gc);
            } else {
                float* pv = &v.x;
#pragma unroll
                for (int j = 0; j < 4; j++) {
                    int g = gc + j;
                    pv[j] = (g < N) ? B[(long)(k0 + row) * N + g] : 0.f;
                }
            }
            uint32_t* bp = &Bs[row * BSTRIDE + c4];
            bp[0] = f2tf(v.x); bp[1] = f2tf(v.y); bp[2] = f2tf(v.z); bp[3] = f2tf(v.w);
        }
        __syncthreads();

        // ---- 4 k8-steps of mma ----
#pragma unroll
        for (int ks = 0; ks < 4; ks++) {
            int kb = ks * 8;
            int kA0 = kb + qc;        // k for a0,a1
            int kA1 = kb + qc + 4;    // k for a2,a3
            int sw0 = ((kA0 >> 2) & 7) << 3;
            int sw1 = ((kA1 >> 2) & 7) << 3;

            uint32_t a[2][4];
#pragma unroll
            for (int i = 0; i < 2; i++) {
                int mb = wm + i * 16;
                a[i][0] = As[kA0 * ASTRIDE + ((mb + qr)     ^ sw0)];
                a[i][1] = As[kA0 * ASTRIDE + ((mb + qr + 8) ^ sw0)];
                a[i][2] = As[kA1 * ASTRIDE + ((mb + qr)     ^ sw1)];
                a[i][3] = As[kA1 * ASTRIDE + ((mb + qr + 8) ^ sw1)];
            }
            uint32_t b[4][2];
#pragma unroll
            for (int j = 0; j < 4; j++) {
                int nb = wn + j * 8;
                b[j][0] = Bs[(kb + qc)     * BSTRIDE + nb + qr];
                b[j][1] = Bs[(kb + qc + 4) * BSTRIDE + nb + qr];
            }
#pragma unroll
            for (int i = 0; i < 2; i++)
#pragma unroll
                for (int j = 0; j < 4; j++)
                    mma_tf32(acc[i][j], a[i], b[j]);
        }
        __syncthreads();
    }

    // ---- epilogue ----
#pragma unroll
    for (int i = 0; i < 2; i++) {
        int r0 = bm + wm + i * 16 + qr;
        int r1 = r0 + 8;
#pragma unroll
        for (int j = 0; j < 4; j++) {
            int c0 = bn + wn + j * 8 + qc * 2;
            if (r0 < M) {
                if (c0     < N) C[(long)r0 * N + c0]     = acc[i][j][0];
                if (c0 + 1 < N) C[(long)r0 * N + c0 + 1] = acc[i][j][1];
            }
            if (r1 < M) {
                if (c0     < N) C[(long)r1 * N + c0]     = acc[i][j][2];
                if (c0 + 1 < N) C[(long)r1 * N + c0 + 1] = acc[i][j][3];
            }
        }
    }
}

// ---------------------------------------------------------
// zero fill
// ---------------------------------------------------------
__global__ void zero_kernel(float* __restrict__ p, long n)
{
    long i = (long)blockIdx.x * blockDim.x + threadIdx.x;
    if (i < n) p[i] = 0.f;
}

// ---------------------------------------------------------
// vector float4 reduction (no return) -- sm_90+
// ---------------------------------------------------------
__device__ __forceinline__ void redAdd4(float4* addr, float4 v)
{
    asm volatile("red.global.add.v4.f32 [%0], {%1,%2,%3,%4};"
                 :: "l"(addr), "f"(v.x), "f"(v.y), "f"(v.z), "f"(v.w)
                 : "memory");
}

// ---------------------------------------------------------
// scatter-add for 256-wide features: agg[dst] += ew * h[src]
// one thread per (edge, float4-chunk), 64 chunks per edge
// ---------------------------------------------------------
__global__ __launch_bounds__(256) void scatter256_kernel(
    const int* __restrict__ src, const int* __restrict__ dst,
    const float* __restrict__ ew,
    const float* __restrict__ h, float* __restrict__ agg)
{
    long t = (long)blockIdx.x * blockDim.x + threadIdx.x;
    long e = t >> 6;
    int  c = (int)(t & 63);
    if (e >= N_EDGES) return;
    int s = src[e];
    int d = dst[e];
    float w = ew[e];
    float4 v = reinterpret_cast<const float4*>(h)[(long)s * 64 + c];
    v.x *= w; v.y *= w; v.z *= w; v.w *= w;
    redAdd4(&reinterpret_cast<float4*>(agg)[(long)d * 64 + c], v);
}

// ---------------------------------------------------------
// scatter-add for 40-wide features (10 float4 chunks per edge)
// ---------------------------------------------------------
__global__ __launch_bounds__(256) void scatter40_kernel(
    const int* __restrict__ src, const int* __restrict__ dst,
    const float* __restrict__ ew,
    const float* __restrict__ h, float* __restrict__ agg)
{
    long t = (long)blockIdx.x * blockDim.x + threadIdx.x;
    long e = t / 10;
    int  c = (int)(t - e * 10);
    if (e >= N_EDGES) return;
    int s = src[e];
    int d = dst[e];
    float w = ew[e];
    float4 v = reinterpret_cast<const float4*>(h)[(long)s * 10 + c];
    v.x *= w; v.y *= w; v.z *= w; v.w *= w;
    redAdd4(&reinterpret_cast<float4*>(agg)[(long)d * 10 + c], v);
}

// ---------------------------------------------------------
// out = log_softmax(out + b), rows of 40, one warp per row
// ---------------------------------------------------------
__global__ __launch_bounds__(256) void logsoftmax40_kernel(
    float* __restrict__ out, const float* __restrict__ b, int M)
{
    int warp = (int)(((long)blockIdx.x * blockDim.x + threadIdx.x) >> 5);
    int lane = threadIdx.x & 31;
    if (warp >= M) return;
    float* row = out + (long)warp * OUT_CH;

    float v0 = row[lane] + b[lane];
    float v1 = (lane < 8) ? (row[32 + lane] + b[32 + lane]) : -INFINITY;

    float m = fmaxf(v0, v1);
#pragma unroll
    for (int o = 16; o > 0; o >>= 1)
        m = fmaxf(m, __shfl_xor_sync(0xFFFFFFFFu, m, o));

    float s = __expf(v0 - m) + ((lane < 8) ? __expf(v1 - m) : 0.f);
#pragma unroll
    for (int o = 16; o > 0; o >>= 1)
        s += __shfl_xor_sync(0xFFFFFFFFu, s, o);

    float lse = m + logf(s);
    row[lane] = v0 - lse;
    if (lane < 8) row[32 + lane] = v1 - lse;
}

// ---------------------------------------------------------
// launch
// ---------------------------------------------------------
extern "C" void kernel_launch(void* const* d_in, const int* in_sizes, int n_in,
                              void* d_out, int out_size)
{
    const float* x  = (const float*)d_in[0];
    const int*   ei = (const int*)d_in[1];
    const float* ew = (const float*)d_in[2];
    const float* W1 = (const float*)d_in[3];
    const float* b1 = (const float*)d_in[4];
    const float* W2 = (const float*)d_in[5];
    const float* b2 = (const float*)d_in[6];
    const float* W3 = (const float*)d_in[7];
    const float* b3 = (const float*)d_in[8];
    float* out = (float*)d_out;

    const int* src = ei;            // edge_index[0]
    const int* dst = ei + N_EDGES;  // edge_index[1]

    float *buf0, *buf1, *buf2;
    cudaGetSymbolAddress((void**)&buf0, g_buf0);
    cudaGetSymbolAddress((void**)&buf1, g_buf1);
    cudaGetSymbolAddress((void**)&buf2, g_buf2);

    const long NF = (long)N_NODES * HID;         // 12.8M
    const long NO = (long)N_NODES * OUT_CH;      // 2M

    const int mtiles = (N_NODES + GBM - 1) / GBM;  // 391
    dim3 gemm_grid1((HID + GBN - 1) / GBN, mtiles);      // 4 x 391
    dim3 gemm_grid3((OUT_CH + GBN - 1) / GBN, mtiles);   // 1 x 391

    const long sc256_threads = (long)N_EDGES * 64;
    const int  sc256_blocks  = (int)((sc256_threads + 255) / 256);
    const long sc40_threads  = (long)N_EDGES * 10;
    const int  sc40_blocks   = (int)((sc40_threads + 255) / 256);

    // ---- layer 1: h1 = x @ W1 ; agg1 = scatter(h1) ----
    gemm_tf32<false><<<gemm_grid1, 256>>>(x, W1, nullptr, buf0, N_NODES, HID, IN_CH);
    zero_kernel<<<(int)((NF + 255) / 256), 256>>>(buf1, NF);
    scatter256_kernel<<<sc256_blocks, 256>>>(src, dst, ew, buf0, buf1);

    // ---- layer 2: h2 = relu(agg1 + b1) @ W2 (bias+relu fused in A-load) ----
    gemm_tf32<true><<<gemm_grid1, 256>>>(buf1, W2, b1, buf0, N_NODES, HID, HID);
    zero_kernel<<<(int)((NF + 255) / 256), 256>>>(buf2, NF);
    scatter256_kernel<<<sc256_blocks, 256>>>(src, dst, ew, buf0, buf2);

    // ---- layer 3: h3 = relu(agg2 + b2) @ W3 ----
    gemm_tf32<true><<<gemm_grid3, 256>>>(buf2, W3, b2, buf0, N_NODES, OUT_CH, HID);
    zero_kernel<<<(int)((NO + 255) / 256), 256>>>(out, NO);
    scatter40_kernel<<<sc40_blocks, 256>>>(src, dst, ew, buf0, out);
    logsoftmax40_kernel<<<(N_NODES * 32 + 255) / 256, 256>>>(out, b3, N_NODES);
}

// round 5
// speedup vs baseline: 2.4249x; 1.5350x over previous
#include <cuda_runtime.h>
#include <cuda_bf16.h>
#include <math.h>
#include <stdint.h>

// Problem constants
#define N_NODES 50000
#define N_EDGES 800000
#define IN_CH   128
#define HID     256
#define OUT_CH  40

// -------- static device scratch (allocation-free) --------
__device__ float g_buf0[(size_t)N_NODES * HID];
__device__ float g_buf1[(size_t)N_NODES * HID];
__device__ float g_buf2[(size_t)N_NODES * HID];

// CSR-by-dst scratch
__device__ int   g_deg[N_NODES];
__device__ int   g_off[N_NODES + 1];
__device__ int   g_pos[N_NODES];
__device__ int   g_csr_src[N_EDGES];
__device__ float g_csr_w[N_EDGES];

// =========================================================
// tf32 tensor-core GEMM: C[M,N] = op(A)[M,K] @ B[K,N]
//   op(A) = FUSE ? relu(A + bias[k]) : A
// =========================================================
#define GBM 128
#define GBN 64
#define GBK 32
#define ASTRIDE 136
#define BSTRIDE 72

__device__ __forceinline__ uint32_t f2tf(float f) {
    uint32_t r;
    asm("cvt.rna.tf32.f32 %0, %1;" : "=r"(r) : "f"(f));
    return r;
}

__device__ __forceinline__ void mma_tf32(float* d, const uint32_t* a, const uint32_t* b) {
    asm volatile(
        "mma.sync.aligned.m16n8k8.row.col.f32.tf32.tf32.f32 "
        "{%0,%1,%2,%3}, {%4,%5,%6,%7}, {%8,%9}, {%0,%1,%2,%3};\n"
        : "+f"(d[0]), "+f"(d[1]), "+f"(d[2]), "+f"(d[3])
        : "r"(a[0]), "r"(a[1]), "r"(a[2]), "r"(a[3]),
          "r"(b[0]), "r"(b[1]));
}

template <bool FUSE>
__global__ __launch_bounds__(256) void gemm_tf32(
    const float* __restrict__ A, const float* __restrict__ B,
    const float* __restrict__ bias, float* __restrict__ C,
    int M, int N, int K)
{
    __shared__ uint32_t As[GBK * ASTRIDE];
    __shared__ uint32_t Bs[GBK * BSTRIDE];

    const int tid  = threadIdx.x;
    const int warp = tid >> 5;
    const int lane = tid & 31;
    const int bm = blockIdx.y * GBM;
    const int bn = blockIdx.x * GBN;

    const int wm = (warp >> 1) * 32;
    const int wn = (warp & 1) * 32;

    const int qr = lane >> 2;
    const int qc = lane & 3;

    float acc[2][4][4];
#pragma unroll
    for (int i = 0; i < 2; i++)
#pragma unroll
        for (int j = 0; j < 4; j++)
#pragma unroll
            for (int t = 0; t < 4; t++) acc[i][j][t] = 0.f;

    for (int k0 = 0; k0 < K; k0 += GBK) {
#pragma unroll
        for (int i = 0; i < 4; i++) {
            int idx = tid + i * 256;
            int row = idx >> 3;
            int c4  = (idx & 7) * 4;
            float4 v = make_float4(0.f, 0.f, 0.f, 0.f);
            int gr = bm + row;
            if (gr < M) {
                v = *reinterpret_cast<const float4*>(A + (long)gr * K + k0 + c4);
                if (FUSE) {
                    v.x = fmaxf(v.x + bias[k0 + c4 + 0], 0.f);
                    v.y = fmaxf(v.y + bias[k0 + c4 + 1], 0.f);
                    v.z = fmaxf(v.z + bias[k0 + c4 + 2], 0.f);
                    v.w = fmaxf(v.w + bias[k0 + c4 + 3], 0.f);
                }
            }
            const float* pv = &v.x;
#pragma unroll
            for (int j = 0; j < 4; j++) {
                int kk = c4 + j;
                int sm = row ^ (((kk >> 2) & 7) << 3);
                As[kk * ASTRIDE + sm] = f2tf(pv[j]);
            }
        }
#pragma unroll
        for (int i = 0; i < 2; i++) {
            int idx = tid + i * 256;
            int row = idx >> 4;
            int c4  = (idx & 15) * 4;
            float4 v = make_float4(0.f, 0.f, 0.f, 0.f);
            int gc = bn + c4;
            if (gc + 3 < N) {
                v = *reinterpret_cast<const float4*>(B + (long)(k0 + row) * N + gc);
            } else {
                float* pv = &v.x;
#pragma unroll
                for (int j = 0; j < 4; j++) {
                    int g = gc + j;
                    pv[j] = (g < N) ? B[(long)(k0 + row) * N + g] : 0.f;
                }
            }
            uint32_t* bp = &Bs[row * BSTRIDE + c4];
            bp[0] = f2tf(v.x); bp[1] = f2tf(v.y); bp[2] = f2tf(v.z); bp[3] = f2tf(v.w);
        }
        __syncthreads();

#pragma unroll
        for (int ks = 0; ks < 4; ks++) {
            int kb = ks * 8;
            int kA0 = kb + qc;
            int kA1 = kb + qc + 4;
            int sw0 = ((kA0 >> 2) & 7) << 3;
            int sw1 = ((kA1 >> 2) & 7) << 3;

            uint32_t a[2][4];
#pragma unroll
            for (int i = 0; i < 2; i++) {
                int mb = wm + i * 16;
                a[i][0] = As[kA0 * ASTRIDE + ((mb + qr)     ^ sw0)];
                a[i][1] = As[kA0 * ASTRIDE + ((mb + qr + 8) ^ sw0)];
                a[i][2] = As[kA1 * ASTRIDE + ((mb + qr)     ^ sw1)];
                a[i][3] = As[kA1 * ASTRIDE + ((mb + qr + 8) ^ sw1)];
            }
            uint32_t b[4][2];
#pragma unroll
            for (int j = 0; j < 4; j++) {
                int nb = wn + j * 8;
                b[j][0] = Bs[(kb + qc)     * BSTRIDE + nb + qr];
                b[j][1] = Bs[(kb + qc + 4) * BSTRIDE + nb + qr];
            }
#pragma unroll
            for (int i = 0; i < 2; i++)
#pragma unroll
                for (int j = 0; j < 4; j++)
                    mma_tf32(acc[i][j], a[i], b[j]);
        }
        __syncthreads();
    }

#pragma unroll
    for (int i = 0; i < 2; i++) {
        int r0 = bm + wm + i * 16 + qr;
        int r1 = r0 + 8;
#pragma unroll
        for (int j = 0; j < 4; j++) {
            int c0 = bn + wn + j * 8 + qc * 2;
            if (r0 < M) {
                if (c0     < N) C[(long)r0 * N + c0]     = acc[i][j][0];
                if (c0 + 1 < N) C[(long)r0 * N + c0 + 1] = acc[i][j][1];
            }
            if (r1 < M) {
                if (c0     < N) C[(long)r1 * N + c0]     = acc[i][j][2];
                if (c0 + 1 < N) C[(long)r1 * N + c0 + 1] = acc[i][j][3];
            }
        }
    }
}

// =========================================================
// CSR build (per call, deterministic work)
// =========================================================
__global__ void zero_deg_kernel()
{
    int i = blockIdx.x * blockDim.x + threadIdx.x;
    if (i < N_NODES) g_deg[i] = 0;
}

__global__ void hist_kernel(const int* __restrict__ dst)
{
    int e = blockIdx.x * blockDim.x + threadIdx.x;
    if (e < N_EDGES) atomicAdd(&g_deg[dst[e]], 1);
}

#define SCAN_T 1024
#define SCAN_C ((N_NODES + SCAN_T - 1) / SCAN_T)   // 49

__global__ __launch_bounds__(SCAN_T) void scan_kernel()
{
    __shared__ int ssum[SCAN_T];
    int t = threadIdx.x;
    int beg = t * SCAN_C;
    int end = min(beg + SCAN_C, N_NODES);
    int local = 0;
    for (int i = beg; i < end; i++) local += g_deg[i];
    ssum[t] = local;
    __syncthreads();
    for (int ofs = 1; ofs < SCAN_T; ofs <<= 1) {
        int add = (t >= ofs) ? ssum[t - ofs] : 0;
        __syncthreads();
        ssum[t] += add;
        __syncthreads();
    }
    int run = (t == 0) ? 0 : ssum[t - 1];
    for (int i = beg; i < end; i++) {
        int d = g_deg[i];
        g_off[i] = run;
        g_pos[i] = run;
        run += d;
    }
    if (t == SCAN_T - 1) g_off[N_NODES] = run;
}

__global__ void fill_kernel(const int* __restrict__ src,
                            const int* __restrict__ dst,
                            const float* __restrict__ ew)
{
    int e = blockIdx.x * blockDim.x + threadIdx.x;
    if (e >= N_EDGES) return;
    int p = atomicAdd(&g_pos[dst[e]], 1);
    g_csr_src[p] = src[e];
    g_csr_w[p]   = ew[e];
}

// =========================================================
// CSR gather: agg[n] = sum_{e in CSR[n]} w_e * h[src_e]
// One warp per (node, 32-float4 slice). C4 = floats/4 per row.
// =========================================================
template <int C4>
__global__ __launch_bounds__(256) void gather_kernel(
    const float* __restrict__ h, float* __restrict__ agg)
{
    const int SLICES = C4 / 32;      // 1 for 128-wide, 2 for 256-wide
    int gw = (int)(((long)blockIdx.x * blockDim.x + threadIdx.x) >> 5);
    int lane = threadIdx.x & 31;
    int n = gw / SLICES;
    int sl = gw - n * SLICES;
    if (n >= N_NODES) return;
    int c = sl * 32 + lane;

    const float4* hp = reinterpret_cast<const float4*>(h);
    int e   = g_off[n];
    int end = g_off[n + 1];

    float4 acc = make_float4(0.f, 0.f, 0.f, 0.f);
    for (; e + 1 < end; e += 2) {
        int   s0 = g_csr_src[e];
        int   s1 = g_csr_src[e + 1];
        float w0 = g_csr_w[e];
        float w1 = g_csr_w[e + 1];
        float4 v0 = hp[(long)s0 * C4 + c];
        float4 v1 = hp[(long)s1 * C4 + c];
        acc.x += w0 * v0.x + w1 * v1.x;
        acc.y += w0 * v0.y + w1 * v1.y;
        acc.z += w0 * v0.z + w1 * v1.z;
        acc.w += w0 * v0.w + w1 * v1.w;
    }
    if (e < end) {
        int   s0 = g_csr_src[e];
        float w0 = g_csr_w[e];
        float4 v0 = hp[(long)s0 * C4 + c];
        acc.x += w0 * v0.x;
        acc.y += w0 * v0.y;
        acc.z += w0 * v0.z;
        acc.w += w0 * v0.w;
    }
    reinterpret_cast<float4*>(agg)[(long)n * C4 + c] = acc;
}

// ---------------------------------------------------------
// zero fill
// ---------------------------------------------------------
__global__ void zero_kernel(float* __restrict__ p, long n)
{
    long i = (long)blockIdx.x * blockDim.x + threadIdx.x;
    if (i < n) p[i] = 0.f;
}

// ---------------------------------------------------------
// vector float4 reduction (no return)
// ---------------------------------------------------------
__device__ __forceinline__ void redAdd4(float4* addr, float4 v)
{
    asm volatile("red.global.add.v4.f32 [%0], {%1,%2,%3,%4};"
                 :: "l"(addr), "f"(v.x), "f"(v.y), "f"(v.z), "f"(v.w)
                 : "memory");
}

// ---------------------------------------------------------
// scatter-add for 40-wide features (10 float4 chunks per edge)
// ---------------------------------------------------------
__global__ __launch_bounds__(256) void scatter40_kernel(
    const int* __restrict__ src, const int* __restrict__ dst,
    const float* __restrict__ ew,
    const float* __restrict__ h, float* __restrict__ agg)
{
    long t = (long)blockIdx.x * blockDim.x + threadIdx.x;
    long e = t / 10;
    int  c = (int)(t - e * 10);
    if (e >= N_EDGES) return;
    int s = src[e];
    int d = dst[e];
    float w = ew[e];
    float4 v = reinterpret_cast<const float4*>(h)[(long)s * 10 + c];
    v.x *= w; v.y *= w; v.z *= w; v.w *= w;
    redAdd4(&reinterpret_cast<float4*>(agg)[(long)d * 10 + c], v);
}

// ---------------------------------------------------------
// out = log_softmax(out + b), rows of 40, one warp per row
// ---------------------------------------------------------
__global__ __launch_bounds__(256) void logsoftmax40_kernel(
    float* __restrict__ out, const float* __restrict__ b, int M)
{
    int warp = (int)(((long)blockIdx.x * blockDim.x + threadIdx.x) >> 5);
    int lane = threadIdx.x & 31;
    if (warp >= M) return;
    float* row = out + (long)warp * OUT_CH;

    float v0 = row[lane] + b[lane];
    float v1 = (lane < 8) ? (row[32 + lane] + b[32 + lane]) : -INFINITY;

    float m = fmaxf(v0, v1);
#pragma unroll
    for (int o = 16; o > 0; o >>= 1)
        m = fmaxf(m, __shfl_xor_sync(0xFFFFFFFFu, m, o));

    float s = __expf(v0 - m) + ((lane < 8) ? __expf(v1 - m) : 0.f);
#pragma unroll
    for (int o = 16; o > 0; o >>= 1)
        s += __shfl_xor_sync(0xFFFFFFFFu, s, o);

    float lse = m + logf(s);
    row[lane] = v0 - lse;
    if (lane < 8) row[32 + lane] = v1 - lse;
}

// ---------------------------------------------------------
// launch
// ---------------------------------------------------------
extern "C" void kernel_launch(void* const* d_in, const int* in_sizes, int n_in,
                              void* d_out, int out_size)
{
    const float* x  = (const float*)d_in[0];
    const int*   ei = (const int*)d_in[1];
    const float* ew = (const float*)d_in[2];
    const float* W1 = (const float*)d_in[3];
    const float* b1 = (const float*)d_in[4];
    const float* W2 = (const float*)d_in[5];
    const float* b2 = (const float*)d_in[6];
    const float* W3 = (const float*)d_in[7];
    const float* b3 = (const float*)d_in[8];
    float* out = (float*)d_out;

    const int* src = ei;            // edge_index[0]
    const int* dst = ei + N_EDGES;  // edge_index[1]

    float *buf0, *buf1, *buf2;
    cudaGetSymbolAddress((void**)&buf0, g_buf0);
    cudaGetSymbolAddress((void**)&buf1, g_buf1);
    cudaGetSymbolAddress((void**)&buf2, g_buf2);

    const long NO = (long)N_NODES * OUT_CH;

    const int mtiles = (N_NODES + GBM - 1) / GBM;
    dim3 gemm_grid1((HID + GBN - 1) / GBN, mtiles);
    dim3 gemm_grid3((OUT_CH + GBN - 1) / GBN, mtiles);

    // ---- build CSR (dst-indexed), reused by all layers ----
    zero_deg_kernel<<<(N_NODES + 255) / 256, 256>>>();
    hist_kernel<<<(N_EDGES + 255) / 256, 256>>>(dst);
    scan_kernel<<<1, SCAN_T>>>();
    fill_kernel<<<(N_EDGES + 255) / 256, 256>>>(src, dst, ew);

    // ---- layer 1 (reordered): agg_x = A_hat @ x ; h1 = agg_x @ W1 ----
    {
        int warps = N_NODES;                     // 1 slice per node (128-wide)
        gather_kernel<32><<<(warps * 32 + 255) / 256, 256>>>(x, buf1);
    }
    gemm_tf32<false><<<gemm_grid1, 256>>>(buf1, W1, nullptr, buf0, N_NODES, HID, IN_CH);

    // ---- layer 2: h2 = relu(h1 + b1) @ W2 ; agg2 = A_hat @ h2 ----
    gemm_tf32<true><<<gemm_grid1, 256>>>(buf0, W2, b1, buf2, N_NODES, HID, HID);
    {
        int warps = N_NODES * 2;                 // 2 slices per node (256-wide)
        gather_kernel<64><<<(warps * 32 + 255) / 256, 256>>>(buf2, buf1);
    }

    // ---- layer 3: h3 = relu(agg2 + b2) @ W3 ; out = scatter(h3) ----
    gemm_tf32<true><<<gemm_grid3, 256>>>(buf1, W3, b2, buf0, N_NODES, OUT_CH, HID);
    zero_kernel<<<(int)((NO + 255) / 256), 256>>>(out, NO);
    {
        const long sc40_threads = (long)N_EDGES * 10;
        scatter40_kernel<<<(int)((sc40_threads + 255) / 256), 256>>>(src, dst, ew, buf0, out);
    }
    logsoftmax40_kernel<<<(N_NODES * 32 + 255) / 256, 256>>>(out, b3, N_NODES);
}